// round 6
// baseline (speedup 1.0000x reference)
#include <cuda_runtime.h>
#include <cuda_bf16.h>
#include <math_constants.h>

// Problem constants (fixed by the reference)
#define NN      4096
#define IN_F    256
#define OUT_F   32
#define NH      8
#define NEG_SLOPE 0.2f
#define MAXN    512   // max neighbors per row (binomial(4096, .004): P(deg>60) ~ 0)

// Scratch (device globals -- no allocation allowed)
__device__ float g_Wh[NH * NN * OUT_F];   // 4 MB, [ (h*N + n)*32 + f ]
__device__ float g_esrc[NH * NN];
__device__ float g_edst[NH * NN];
__device__ int   g_adj_fmt;               // 0=uint8, 1=int32, 2=float32

// ---------------------------------------------------------------------------
// Format detection: classify adjacency element width from byte patterns.
// Input-determined -> same result every call (deterministic, graph-safe).
// ---------------------------------------------------------------------------
__global__ void detect_fmt_kernel(const unsigned char* __restrict__ adj) {
    __shared__ unsigned s1, s3;
    if (threadIdx.x == 0) { s1 = 0u; s3 = 0u; }
    __syncthreads();
    unsigned l1 = 0u, l3 = 0u;
    const uint4* p = (const uint4*)adj;
    const unsigned M1 = 0x0000FF00u;   // byte offset %4 == 1
    const unsigned M3 = 0xFF000000u;   // byte offset %4 == 3
    // scan first 1 MB
    for (int idx = threadIdx.x; idx < (1 << 20) / 16; idx += blockDim.x) {
        uint4 v = p[idx];
        l1 |= (v.x & M1) | (v.y & M1) | (v.z & M1) | (v.w & M1);
        l3 |= (v.x & M3) | (v.y & M3) | (v.z & M3) | (v.w & M3);
    }
    if (l1) atomicOr(&s1, 1u);
    if (l3) atomicOr(&s3, 1u);
    __syncthreads();
    if (threadIdx.x == 0)
        g_adj_fmt = s1 ? 0 : (s3 ? 2 : 1);
}

// ---------------------------------------------------------------------------
// Kernel A: Wh = einsum('hif,ni->hnf'), plus e_src/e_dst epilogue.
// Block: 256 threads, thread t -> (h = t>>5, f = t&31). 8 nodes per block.
// ---------------------------------------------------------------------------
#define NODES_PER_BLK 8
__global__ void __launch_bounds__(256) wh_kernel(
    const float* __restrict__ x,      // (N, IN_F)
    const float* __restrict__ W,      // (H, IN_F, OUT_F)
    const float* __restrict__ a_src,  // (H, OUT_F)
    const float* __restrict__ a_dst)  // (H, OUT_F)
{
    __shared__ float xs[NODES_PER_BLK][IN_F];
    const int tid = threadIdx.x;
    const int h = tid >> 5;
    const int f = tid & 31;
    const int n0 = blockIdx.x * NODES_PER_BLK;

#pragma unroll
    for (int r = 0; r < NODES_PER_BLK; r++)
        xs[r][tid] = x[(n0 + r) * IN_F + tid];
    __syncthreads();

    float acc[NODES_PER_BLK];
#pragma unroll
    for (int r = 0; r < NODES_PER_BLK; r++) acc[r] = 0.0f;

    const float* Wp = W + h * (IN_F * OUT_F) + f;  // stride OUT_F over i
#pragma unroll 4
    for (int i = 0; i < IN_F; i++) {
        const float wv = Wp[i * OUT_F];            // warp reads 128B contiguous
#pragma unroll
        for (int r = 0; r < NODES_PER_BLK; r++)
            acc[r] = fmaf(xs[r][i], wv, acc[r]);
    }

    const float asv = a_src[h * OUT_F + f];
    const float adv = a_dst[h * OUT_F + f];

#pragma unroll
    for (int r = 0; r < NODES_PER_BLK; r++) {
        const int n = n0 + r;
        g_Wh[(h * NN + n) * OUT_F + f] = acc[r];
        float es = acc[r] * asv;
        float ed = acc[r] * adv;
#pragma unroll
        for (int o = 16; o > 0; o >>= 1) {
            es += __shfl_xor_sync(0xFFFFFFFFu, es, o);
            ed += __shfl_xor_sync(0xFFFFFFFFu, ed, o);
        }
        if (f == 0) {
            g_esrc[h * NN + n] = es;
            g_edst[h * NN + n] = ed;
        }
    }
}

// ---------------------------------------------------------------------------
// Kernel B: per destination row i -- build neighbor list (deterministic,
// ascending order via prefix scan), then per-head softmax + aggregation.
// Block: 256 threads = 8 warps; warp w handles head w.
// ---------------------------------------------------------------------------
__global__ void __launch_bounds__(256) gat_kernel(
    const unsigned char* __restrict__ adj,   // (N, N), element width per g_adj_fmt
    const float* __restrict__ bias,          // (H*OUT_F,)
    float* __restrict__ out)                 // (N, H*OUT_F)
{
    __shared__ int   s_nbr[MAXN];
    __shared__ float s_p[NH][MAXN];      // 16 KB: per-head logits then probs
    __shared__ int   s_woff[8];          // per-warp exclusive offsets
    __shared__ int   s_total;

    const int i    = blockIdx.x;
    const int tid  = threadIdx.x;
    const int lane = tid & 31;
    const int wid  = tid >> 5;

    // ---- Phase 1: scan adjacency row. Each thread owns 16 columns. ----
    const int base = tid * 16;
    const int fmt = g_adj_fmt;
    bool keep[16];

    if (fmt == 1) {
        // int32 elements: 16 ints = 4 x int4, coalesced
        const int4* row = (const int4*)((const int*)adj + (size_t)i * NN) + tid * 4;
        int4 v0 = row[0], v1 = row[1], v2 = row[2], v3 = row[3];
        int vals[16] = {v0.x, v0.y, v0.z, v0.w, v1.x, v1.y, v1.z, v1.w,
                        v2.x, v2.y, v2.z, v2.w, v3.x, v3.y, v3.z, v3.w};
#pragma unroll
        for (int k = 0; k < 16; k++)
            keep[k] = (vals[k] != 0) || (base + k == i);
    } else if (fmt == 2) {
        // float32 elements
        const float4* row = (const float4*)((const float*)adj + (size_t)i * NN) + tid * 4;
        float4 v0 = row[0], v1 = row[1], v2 = row[2], v3 = row[3];
        float vals[16] = {v0.x, v0.y, v0.z, v0.w, v1.x, v1.y, v1.z, v1.w,
                          v2.x, v2.y, v2.z, v2.w, v3.x, v3.y, v3.z, v3.w};
#pragma unroll
        for (int k = 0; k < 16; k++)
            keep[k] = (vals[k] != 0.0f) || (base + k == i);
    } else {
        // uint8 elements: 16 bytes = 1 x int4
        union { int4 v; unsigned char b[16]; } u;
        u.v = ((const int4*)(adj + (size_t)i * NN))[tid];
#pragma unroll
        for (int k = 0; k < 16; k++)
            keep[k] = (u.b[k] != 0) || (base + k == i);
    }

    int cnt = 0;
#pragma unroll
    for (int k = 0; k < 16; k++) cnt += keep[k] ? 1 : 0;

    // Inclusive warp scan of cnt
    int ws = cnt;
#pragma unroll
    for (int o = 1; o < 32; o <<= 1) {
        int v = __shfl_up_sync(0xFFFFFFFFu, ws, o);
        if (lane >= o) ws += v;
    }
    if (lane == 31) s_woff[wid] = ws;   // warp totals
    __syncthreads();
    if (wid == 0) {
        int v = (lane < 8) ? s_woff[lane] : 0;
        int sc = v;
#pragma unroll
        for (int o = 1; o < 8; o <<= 1) {
            int t = __shfl_up_sync(0xFFFFFFFFu, sc, o);
            if (lane >= o) sc += t;
        }
        if (lane < 8) s_woff[lane] = sc - v;   // exclusive warp offsets
        if (lane == 7) s_total = sc;           // grand total
    }
    __syncthreads();

    int off = s_woff[wid] + ws - cnt;  // this thread's exclusive start
#pragma unroll
    for (int k = 0; k < 16; k++) {
        if (keep[k]) {
            if (off < MAXN) s_nbr[off] = base + k;
            off++;
        }
    }
    __syncthreads();

    const int d = (s_total < MAXN) ? s_total : MAXN;   // always >= 1 (self-loop)

    // ---- Phase 2: per-head softmax over the d neighbors ----
    const int h = wid;
    const float esi = g_esrc[h * NN + i];
    const float* __restrict__ edst_h = g_edst + h * NN;

    float m = -CUDART_INF_F;
    for (int k = lane; k < d; k += 32) {
        float e = esi + edst_h[s_nbr[k]];
        e = (e >= 0.0f) ? e : NEG_SLOPE * e;   // LeakyReLU
        s_p[h][k] = e;
        m = fmaxf(m, e);
    }
#pragma unroll
    for (int o = 16; o > 0; o >>= 1)
        m = fmaxf(m, __shfl_xor_sync(0xFFFFFFFFu, m, o));

    float s = 0.0f;
    for (int k = lane; k < d; k += 32) {
        float p = __expf(s_p[h][k] - m);
        s_p[h][k] = p;
        s += p;
    }
#pragma unroll
    for (int o = 16; o > 0; o >>= 1)
        s += __shfl_xor_sync(0xFFFFFFFFu, s, o);
    const float inv = 1.0f / s;
    __syncwarp();

    // ---- Phase 3: weighted aggregation. lane = feature f. ----
    const float* __restrict__ Wh_h = g_Wh + (size_t)h * NN * OUT_F;
    float acc = 0.0f;
    for (int k = 0; k < d; k++) {
        const int j = s_nbr[k];                // smem broadcast
        const float p = s_p[h][k];             // smem broadcast
        acc = fmaf(p, Wh_h[j * OUT_F + lane], acc);   // 128B coalesced, L2-hit
    }
    out[(size_t)i * (NH * OUT_F) + h * OUT_F + lane] =
        acc * inv + bias[h * OUT_F + lane];
}

// ---------------------------------------------------------------------------
extern "C" void kernel_launch(void* const* d_in, const int* in_sizes, int n_in,
                              void* d_out, int out_size) {
    const float*         x     = (const float*)d_in[0];
    const unsigned char* adj   = (const unsigned char*)d_in[1];
    const float*         W     = (const float*)d_in[2];
    const float*         a_src = (const float*)d_in[3];
    const float*         a_dst = (const float*)d_in[4];
    const float*         bias  = (const float*)d_in[5];
    float*               out   = (float*)d_out;

    detect_fmt_kernel<<<1, 256>>>(adj);
    wh_kernel<<<NN / NODES_PER_BLK, 256>>>(x, W, a_src, a_dst);
    gat_kernel<<<NN, 256>>>(adj, bias, out);
}

// round 8
// speedup vs baseline: 1.4255x; 1.4255x over previous
#include <cuda_runtime.h>
#include <cuda_bf16.h>
#include <math_constants.h>

// Problem constants (fixed by the reference)
#define NN      4096
#define IN_F    256
#define OUT_F   32
#define NH      8
#define NEG_SLOPE 0.2f
#define MAXN    512   // max neighbors per row (binomial(4096, .004): P(deg>60) ~ 0)

// Scratch (device globals -- no allocation allowed)
__device__ float g_Wh[NH * NN * OUT_F];   // 4 MB, [ (h*N + n)*32 + f ]
__device__ float g_esrc[NH * NN];
__device__ float g_edst[NH * NN];
__device__ int   g_adj_fmt;               // 0=uint8, 1=int32, 2=float32

// ---------------------------------------------------------------------------
// Format detection: classify adjacency element width from byte patterns.
// Scans 128 KB with 1024 threads x 8 iters (full MLP, ~2 DRAM round-trips).
// P(misclassify) ~ e^-131 for both uint8 and float32 cases.
// Input-determined -> same result every call (deterministic, graph-safe).
// ---------------------------------------------------------------------------
__global__ void __launch_bounds__(1024) detect_fmt_kernel(const unsigned char* __restrict__ adj) {
    __shared__ unsigned s1, s3;
    if (threadIdx.x == 0) { s1 = 0u; s3 = 0u; }
    __syncthreads();
    unsigned l1 = 0u, l3 = 0u;
    const uint4* p = (const uint4*)adj;
    const unsigned M1 = 0x0000FF00u;   // byte offset %4 == 1
    const unsigned M3 = 0xFF000000u;   // byte offset %4 == 3
    // scan first 128 KB: 8192 uint4, 1024 threads -> 8 independent loads each
#pragma unroll
    for (int it = 0; it < 8; it++) {
        uint4 v = p[it * 1024 + threadIdx.x];
        l1 |= (v.x & M1) | (v.y & M1) | (v.z & M1) | (v.w & M1);
        l3 |= (v.x & M3) | (v.y & M3) | (v.z & M3) | (v.w & M3);
    }
    if (l1) atomicOr(&s1, 1u);
    if (l3) atomicOr(&s3, 1u);
    __syncthreads();
    if (threadIdx.x == 0)
        g_adj_fmt = s1 ? 0 : (s3 ? 2 : 1);
}

// ---------------------------------------------------------------------------
// Kernel A: Wh = einsum('hif,ni->hnf'), plus e_src/e_dst epilogue.
// Block: 256 threads, thread t -> (h = t>>5, f = t&31). 8 nodes per block.
// ---------------------------------------------------------------------------
#define NODES_PER_BLK 8
__global__ void __launch_bounds__(256) wh_kernel(
    const float* __restrict__ x,      // (N, IN_F)
    const float* __restrict__ W,      // (H, IN_F, OUT_F)
    const float* __restrict__ a_src,  // (H, OUT_F)
    const float* __restrict__ a_dst)  // (H, OUT_F)
{
    __shared__ float xs[NODES_PER_BLK][IN_F];
    const int tid = threadIdx.x;
    const int h = tid >> 5;
    const int f = tid & 31;
    const int n0 = blockIdx.x * NODES_PER_BLK;

#pragma unroll
    for (int r = 0; r < NODES_PER_BLK; r++)
        xs[r][tid] = x[(n0 + r) * IN_F + tid];
    __syncthreads();

    float acc[NODES_PER_BLK];
#pragma unroll
    for (int r = 0; r < NODES_PER_BLK; r++) acc[r] = 0.0f;

    const float* Wp = W + h * (IN_F * OUT_F) + f;  // stride OUT_F over i
#pragma unroll 4
    for (int i = 0; i < IN_F; i++) {
        const float wv = Wp[i * OUT_F];            // warp reads 128B contiguous
#pragma unroll
        for (int r = 0; r < NODES_PER_BLK; r++)
            acc[r] = fmaf(xs[r][i], wv, acc[r]);
    }

    const float asv = a_src[h * OUT_F + f];
    const float adv = a_dst[h * OUT_F + f];

#pragma unroll
    for (int r = 0; r < NODES_PER_BLK; r++) {
        const int n = n0 + r;
        g_Wh[(h * NN + n) * OUT_F + f] = acc[r];
        float es = acc[r] * asv;
        float ed = acc[r] * adv;
#pragma unroll
        for (int o = 16; o > 0; o >>= 1) {
            es += __shfl_xor_sync(0xFFFFFFFFu, es, o);
            ed += __shfl_xor_sync(0xFFFFFFFFu, ed, o);
        }
        if (f == 0) {
            g_esrc[h * NN + n] = es;
            g_edst[h * NN + n] = ed;
        }
    }
}

// ---------------------------------------------------------------------------
// Kernel B: per destination row i -- build neighbor list (deterministic,
// ascending order via prefix scan), then per-head softmax + aggregation.
// Block: 256 threads = 8 warps; warp w handles head w.
// ---------------------------------------------------------------------------
__global__ void __launch_bounds__(256) gat_kernel(
    const unsigned char* __restrict__ adj,   // (N, N), element width per g_adj_fmt
    const float* __restrict__ bias,          // (H*OUT_F,)
    float* __restrict__ out)                 // (N, H*OUT_F)
{
    __shared__ int   s_nbr[MAXN];
    __shared__ float s_p[NH][MAXN];      // 16 KB: per-head logits then probs
    __shared__ int   s_woff[8];          // per-warp exclusive offsets
    __shared__ int   s_total;

    const int i    = blockIdx.x;
    const int tid  = threadIdx.x;
    const int lane = tid & 31;
    const int wid  = tid >> 5;

    // ---- Phase 1: scan adjacency row. Each thread owns 16 columns. ----
    const int base = tid * 16;
    const int fmt = g_adj_fmt;
    bool keep[16];

    if (fmt == 1) {
        // int32 elements: 16 ints = 4 x int4, coalesced
        const int4* row = (const int4*)((const int*)adj + (size_t)i * NN) + tid * 4;
        int4 v0 = row[0], v1 = row[1], v2 = row[2], v3 = row[3];
        int vals[16] = {v0.x, v0.y, v0.z, v0.w, v1.x, v1.y, v1.z, v1.w,
                        v2.x, v2.y, v2.z, v2.w, v3.x, v3.y, v3.z, v3.w};
#pragma unroll
        for (int k = 0; k < 16; k++)
            keep[k] = (vals[k] != 0) || (base + k == i);
    } else if (fmt == 2) {
        // float32 elements
        const float4* row = (const float4*)((const float*)adj + (size_t)i * NN) + tid * 4;
        float4 v0 = row[0], v1 = row[1], v2 = row[2], v3 = row[3];
        float vals[16] = {v0.x, v0.y, v0.z, v0.w, v1.x, v1.y, v1.z, v1.w,
                          v2.x, v2.y, v2.z, v2.w, v3.x, v3.y, v3.z, v3.w};
#pragma unroll
        for (int k = 0; k < 16; k++)
            keep[k] = (vals[k] != 0.0f) || (base + k == i);
    } else {
        // uint8 elements: 16 bytes = 1 x int4
        union { int4 v; unsigned char b[16]; } u;
        u.v = ((const int4*)(adj + (size_t)i * NN))[tid];
#pragma unroll
        for (int k = 0; k < 16; k++)
            keep[k] = (u.b[k] != 0) || (base + k == i);
    }

    int cnt = 0;
#pragma unroll
    for (int k = 0; k < 16; k++) cnt += keep[k] ? 1 : 0;

    // Inclusive warp scan of cnt
    int ws = cnt;
#pragma unroll
    for (int o = 1; o < 32; o <<= 1) {
        int v = __shfl_up_sync(0xFFFFFFFFu, ws, o);
        if (lane >= o) ws += v;
    }
    if (lane == 31) s_woff[wid] = ws;   // warp totals
    __syncthreads();
    if (wid == 0) {
        int v = (lane < 8) ? s_woff[lane] : 0;
        int sc = v;
#pragma unroll
        for (int o = 1; o < 8; o <<= 1) {
            int t = __shfl_up_sync(0xFFFFFFFFu, sc, o);
            if (lane >= o) sc += t;
        }
        if (lane < 8) s_woff[lane] = sc - v;   // exclusive warp offsets
        if (lane == 7) s_total = sc;           // grand total
    }
    __syncthreads();

    int off = s_woff[wid] + ws - cnt;  // this thread's exclusive start
#pragma unroll
    for (int k = 0; k < 16; k++) {
        if (keep[k]) {
            if (off < MAXN) s_nbr[off] = base + k;
            off++;
        }
    }
    __syncthreads();

    const int d = (s_total < MAXN) ? s_total : MAXN;   // always >= 1 (self-loop)

    // ---- Phase 2: per-head softmax over the d neighbors ----
    const int h = wid;
    const float esi = g_esrc[h * NN + i];
    const float* __restrict__ edst_h = g_edst + h * NN;

    float m = -CUDART_INF_F;
    for (int k = lane; k < d; k += 32) {
        float e = esi + edst_h[s_nbr[k]];
        e = (e >= 0.0f) ? e : NEG_SLOPE * e;   // LeakyReLU
        s_p[h][k] = e;
        m = fmaxf(m, e);
    }
#pragma unroll
    for (int o = 16; o > 0; o >>= 1)
        m = fmaxf(m, __shfl_xor_sync(0xFFFFFFFFu, m, o));

    float s = 0.0f;
    for (int k = lane; k < d; k += 32) {
        float p = __expf(s_p[h][k] - m);
        s_p[h][k] = p;
        s += p;
    }
#pragma unroll
    for (int o = 16; o > 0; o >>= 1)
        s += __shfl_xor_sync(0xFFFFFFFFu, s, o);
    const float inv = 1.0f / s;
    __syncwarp();

    // ---- Phase 3: weighted aggregation. lane = feature f. ----
    const float* __restrict__ Wh_h = g_Wh + (size_t)h * NN * OUT_F;
    float acc = 0.0f;
    for (int k = 0; k < d; k++) {
        const int j = s_nbr[k];                // smem broadcast
        const float p = s_p[h][k];             // smem broadcast
        acc = fmaf(p, Wh_h[j * OUT_F + lane], acc);   // 128B coalesced, L2-hit
    }
    out[(size_t)i * (NH * OUT_F) + h * OUT_F + lane] =
        acc * inv + bias[h * OUT_F + lane];
}

// ---------------------------------------------------------------------------
extern "C" void kernel_launch(void* const* d_in, const int* in_sizes, int n_in,
                              void* d_out, int out_size) {
    const float*         x     = (const float*)d_in[0];
    const unsigned char* adj   = (const unsigned char*)d_in[1];
    const float*         W     = (const float*)d_in[2];
    const float*         a_src = (const float*)d_in[3];
    const float*         a_dst = (const float*)d_in[4];
    const float*         bias  = (const float*)d_in[5];
    float*               out   = (float*)d_out;

    detect_fmt_kernel<<<1, 1024>>>(adj);
    wh_kernel<<<NN / NODES_PER_BLK, 256>>>(x, W, a_src, a_dst);
    gat_kernel<<<NN, 256>>>(adj, bias, out);
}

// round 10
// speedup vs baseline: 1.5486x; 1.0863x over previous
#include <cuda_runtime.h>
#include <cuda_bf16.h>
#include <math_constants.h>

// Problem constants (fixed by the reference)
#define NN      4096
#define IN_F    256
#define OUT_F   32
#define NH      8
#define NEG_SLOPE 0.2f
#define MAXN    512   // max neighbors per row (binomial(4096, .004): P(deg>60) ~ 0)

// Scratch (device globals -- no allocation allowed)
__device__ float g_Wh[NH * NN * OUT_F];   // 4 MB, [ (h*N + n)*32 + f ]
__device__ float g_esrc[NH * NN];
__device__ float g_edst[NH * NN];
__device__ int   g_adj_fmt;               // 0=uint8, 1=int32, 2=float32

// ---------------------------------------------------------------------------
// Kernel A: Wh = einsum('hif,ni->hnf'), plus e_src/e_dst epilogue.
// Block: 256 threads, thread t -> (h = t>>5, f = t&31). 8 nodes per block.
// Inner loop vectorized over i in groups of 4 (float4 smem loads).
// Block 0 additionally classifies the adjacency dtype (writes g_adj_fmt,
// consumed by gat_kernel after the kernel boundary).
// ---------------------------------------------------------------------------
#define NODES_PER_BLK 8
__global__ void __launch_bounds__(256) wh_kernel(
    const float* __restrict__ x,      // (N, IN_F)
    const float* __restrict__ W,      // (H, IN_F, OUT_F)
    const float* __restrict__ a_src,  // (H, OUT_F)
    const float* __restrict__ a_dst,  // (H, OUT_F)
    const unsigned char* __restrict__ adj)
{
    __shared__ float4 xs4[NODES_PER_BLK][IN_F / 4];   // 8 KB
    __shared__ unsigned s_det[2];

    const int tid = threadIdx.x;
    const int h = tid >> 5;
    const int f = tid & 31;
    const int n0 = blockIdx.x * NODES_PER_BLK;

    // ---- Format detection (block 0 only): scan first 32 KB of adj ----
    // uint8 bools -> nonzero bytes at offset%4==1 (~33 expected, P(none)=e^-33)
    // float32 1.0f -> bytes 00 00 80 3F: nonzero only at %4 in {2,3}
    // int32 1      -> nonzero only at %4==0
    if (blockIdx.x == 0) {
        if (tid < 2) s_det[tid] = 0u;
        __syncthreads();
        unsigned l1 = 0u, l3 = 0u;
        const uint4* p = (const uint4*)adj;
        const unsigned M1 = 0x0000FF00u, M3 = 0xFF000000u;
#pragma unroll
        for (int it = 0; it < 8; it++) {
            uint4 v = p[it * 256 + tid];          // 32 KB total
            l1 |= (v.x & M1) | (v.y & M1) | (v.z & M1) | (v.w & M1);
            l3 |= (v.x & M3) | (v.y & M3) | (v.z & M3) | (v.w & M3);
        }
        if (l1) atomicOr(&s_det[0], 1u);
        if (l3) atomicOr(&s_det[1], 1u);
        __syncthreads();
        if (tid == 0)
            g_adj_fmt = s_det[0] ? 0 : (s_det[1] ? 2 : 1);
    }

    // ---- Load 8 x-rows into smem as float4 (coalesced) ----
    const float4* x4 = (const float4*)x;
#pragma unroll
    for (int t = tid; t < NODES_PER_BLK * (IN_F / 4); t += 256) {
        const int r = t >> 6;          // /64
        const int j = t & 63;
        xs4[r][j] = x4[(size_t)(n0 + r) * (IN_F / 4) + j];
    }
    __syncthreads();

    float acc[NODES_PER_BLK];
#pragma unroll
    for (int r = 0; r < NODES_PER_BLK; r++) acc[r] = 0.0f;

    const float* Wp = W + h * (IN_F * OUT_F) + f;  // stride OUT_F over i
#pragma unroll 4
    for (int i4 = 0; i4 < IN_F / 4; i4++) {
        const float w0 = Wp[(4 * i4 + 0) * OUT_F];  // warp-coalesced 128B
        const float w1 = Wp[(4 * i4 + 1) * OUT_F];
        const float w2 = Wp[(4 * i4 + 2) * OUT_F];
        const float w3 = Wp[(4 * i4 + 3) * OUT_F];
#pragma unroll
        for (int r = 0; r < NODES_PER_BLK; r++) {
            const float4 xv = xs4[r][i4];          // 1 LDS.128, warp broadcast
            acc[r] = fmaf(xv.x, w0,
                     fmaf(xv.y, w1,
                     fmaf(xv.z, w2,
                     fmaf(xv.w, w3, acc[r]))));
        }
    }

    const float asv = a_src[h * OUT_F + f];
    const float adv = a_dst[h * OUT_F + f];

#pragma unroll
    for (int r = 0; r < NODES_PER_BLK; r++) {
        const int n = n0 + r;
        g_Wh[(h * NN + n) * OUT_F + f] = acc[r];
        float es = acc[r] * asv;
        float ed = acc[r] * adv;
#pragma unroll
        for (int o = 16; o > 0; o >>= 1) {
            es += __shfl_xor_sync(0xFFFFFFFFu, es, o);
            ed += __shfl_xor_sync(0xFFFFFFFFu, ed, o);
        }
        if (f == 0) {
            g_esrc[h * NN + n] = es;
            g_edst[h * NN + n] = ed;
        }
    }
}

// ---------------------------------------------------------------------------
// Kernel B: per destination row i -- build neighbor list (deterministic,
// ascending order via prefix scan), then per-head softmax + aggregation.
// Block: 256 threads = 8 warps; warp w handles head w.
// ---------------------------------------------------------------------------
__global__ void __launch_bounds__(256) gat_kernel(
    const unsigned char* __restrict__ adj,   // (N, N), element width per g_adj_fmt
    const float* __restrict__ bias,          // (H*OUT_F,)
    float* __restrict__ out)                 // (N, H*OUT_F)
{
    __shared__ int   s_nbr[MAXN];
    __shared__ float s_p[NH][MAXN];      // 16 KB: per-head logits then probs
    __shared__ int   s_woff[8];          // per-warp exclusive offsets
    __shared__ int   s_total;

    const int i    = blockIdx.x;
    const int tid  = threadIdx.x;
    const int lane = tid & 31;
    const int wid  = tid >> 5;

    // ---- Phase 1: scan adjacency row (streaming loads). 16 cols/thread. ----
    const int base = tid * 16;
    const int fmt = g_adj_fmt;
    bool keep[16];

    if (fmt == 1) {
        const int4* row = (const int4*)((const int*)adj + (size_t)i * NN) + tid * 4;
        int4 v0 = __ldcs(row + 0), v1 = __ldcs(row + 1);
        int4 v2 = __ldcs(row + 2), v3 = __ldcs(row + 3);
        int vals[16] = {v0.x, v0.y, v0.z, v0.w, v1.x, v1.y, v1.z, v1.w,
                        v2.x, v2.y, v2.z, v2.w, v3.x, v3.y, v3.z, v3.w};
#pragma unroll
        for (int k = 0; k < 16; k++)
            keep[k] = (vals[k] != 0) || (base + k == i);
    } else if (fmt == 2) {
        const float4* row = (const float4*)((const float*)adj + (size_t)i * NN) + tid * 4;
        float4 v0 = __ldcs(row + 0), v1 = __ldcs(row + 1);
        float4 v2 = __ldcs(row + 2), v3 = __ldcs(row + 3);
        float vals[16] = {v0.x, v0.y, v0.z, v0.w, v1.x, v1.y, v1.z, v1.w,
                          v2.x, v2.y, v2.z, v2.w, v3.x, v3.y, v3.z, v3.w};
#pragma unroll
        for (int k = 0; k < 16; k++)
            keep[k] = (vals[k] != 0.0f) || (base + k == i);
    } else {
        union { int4 v; unsigned char b[16]; } u;
        u.v = __ldcs((const int4*)(adj + (size_t)i * NN) + tid);
#pragma unroll
        for (int k = 0; k < 16; k++)
            keep[k] = (u.b[k] != 0) || (base + k == i);
    }

    int cnt = 0;
#pragma unroll
    for (int k = 0; k < 16; k++) cnt += keep[k] ? 1 : 0;

    // Inclusive warp scan of cnt
    int ws = cnt;
#pragma unroll
    for (int o = 1; o < 32; o <<= 1) {
        int v = __shfl_up_sync(0xFFFFFFFFu, ws, o);
        if (lane >= o) ws += v;
    }
    if (lane == 31) s_woff[wid] = ws;   // warp totals
    __syncthreads();
    if (wid == 0) {
        int v = (lane < 8) ? s_woff[lane] : 0;
        int sc = v;
#pragma unroll
        for (int o = 1; o < 8; o <<= 1) {
            int t = __shfl_up_sync(0xFFFFFFFFu, sc, o);
            if (lane >= o) sc += t;
        }
        if (lane < 8) s_woff[lane] = sc - v;   // exclusive warp offsets
        if (lane == 7) s_total = sc;           // grand total
    }
    __syncthreads();

    int off = s_woff[wid] + ws - cnt;  // this thread's exclusive start
#pragma unroll
    for (int k = 0; k < 16; k++) {
        if (keep[k]) {
            if (off < MAXN) s_nbr[off] = base + k;
            off++;
        }
    }
    __syncthreads();

    const int d = (s_total < MAXN) ? s_total : MAXN;   // always >= 1 (self-loop)

    // ---- Phase 2: per-head softmax over the d neighbors ----
    const int h = wid;
    const float esi = g_esrc[h * NN + i];
    const float* __restrict__ edst_h = g_edst + h * NN;

    float m = -CUDART_INF_F;
    for (int k = lane; k < d; k += 32) {
        float e = esi + edst_h[s_nbr[k]];
        e = (e >= 0.0f) ? e : NEG_SLOPE * e;   // LeakyReLU
        s_p[h][k] = e;
        m = fmaxf(m, e);
    }
#pragma unroll
    for (int o = 16; o > 0; o >>= 1)
        m = fmaxf(m, __shfl_xor_sync(0xFFFFFFFFu, m, o));

    float s = 0.0f;
    for (int k = lane; k < d; k += 32) {
        float p = __expf(s_p[h][k] - m);
        s_p[h][k] = p;
        s += p;
    }
#pragma unroll
    for (int o = 16; o > 0; o >>= 1)
        s += __shfl_xor_sync(0xFFFFFFFFu, s, o);
    const float inv = 1.0f / s;
    __syncwarp();

    // ---- Phase 3: weighted aggregation, unroll-2 for MLP. lane = f. ----
    const float* __restrict__ Wh_h = g_Wh + (size_t)h * NN * OUT_F;
    float acc = 0.0f;
    int k = 0;
    for (; k + 2 <= d; k += 2) {
        const int j0 = s_nbr[k], j1 = s_nbr[k + 1];
        const float p0 = s_p[h][k], p1 = s_p[h][k + 1];
        const float v0 = Wh_h[j0 * OUT_F + lane];
        const float v1 = Wh_h[j1 * OUT_F + lane];
        acc = fmaf(p0, v0, acc);
        acc = fmaf(p1, v1, acc);
    }
    if (k < d) {
        const int j = s_nbr[k];
        acc = fmaf(s_p[h][k], Wh_h[j * OUT_F + lane], acc);
    }
    out[(size_t)i * (NH * OUT_F) + h * OUT_F + lane] =
        acc * inv + bias[h * OUT_F + lane];
}

// ---------------------------------------------------------------------------
extern "C" void kernel_launch(void* const* d_in, const int* in_sizes, int n_in,
                              void* d_out, int out_size) {
    const float*         x     = (const float*)d_in[0];
    const unsigned char* adj   = (const unsigned char*)d_in[1];
    const float*         W     = (const float*)d_in[2];
    const float*         a_src = (const float*)d_in[3];
    const float*         a_dst = (const float*)d_in[4];
    const float*         bias  = (const float*)d_in[5];
    float*               out   = (float*)d_out;

    wh_kernel<<<NN / NODES_PER_BLK, 256>>>(x, W, a_src, a_dst, adj);
    gat_kernel<<<NN, 256>>>(adj, bias, out);
}